// round 2
// baseline (speedup 1.0000x reference)
#include <cuda_runtime.h>
#include <cstdint>

#define HDIM 1024
#define NEXP 64
#define KTOP 8
#define BM   128
#define BK   16
#define XST  20   // smem row stride (floats) for X tile (128x16, padded)
#define WST  20   // smem row stride (floats) for W tile (64x16, padded)
#define NTHREADS 512

__device__ float g_esum[NEXP];
__device__ int   g_ecnt[NEXP];

__global__ void zero_k() {
    int t = threadIdx.x;
    if (t < NEXP) { g_esum[t] = 0.0f; g_ecnt[t] = 0; }
}

__device__ __forceinline__ unsigned smem_u32(const void* p) {
    return (unsigned)__cvta_generic_to_shared(p);
}
__device__ __forceinline__ void cp16(unsigned dst, const void* src) {
    asm volatile("cp.async.cg.shared.global [%0], [%1], 16;\n" :: "r"(dst), "l"(src));
}
__device__ __forceinline__ void cp_commit() { asm volatile("cp.async.commit_group;\n"); }
__device__ __forceinline__ void cp_wait0()  { asm volatile("cp.async.wait_group 0;\n" ::: "memory"); }

// packed f32x2 FMA: d = a*b + d (componentwise)
__device__ __forceinline__ void fma2(unsigned long long& d,
                                     unsigned long long a,
                                     unsigned long long b) {
    asm("fma.rn.f32x2 %0, %1, %2, %3;" : "=l"(d) : "l"(a), "l"(b), "l"(d));
}

__device__ __forceinline__ float2 unpack2(unsigned long long v) {
    float2 f;
    asm("mov.b64 {%0, %1}, %2;" : "=f"(f.x), "=f"(f.y) : "l"(v));
    return f;
}

__global__ __launch_bounds__(NTHREADS, 1)
void gate_k(const float* __restrict__ X, const float* __restrict__ W,
            float* __restrict__ outIdx, float* __restrict__ outW, int N) {
    // union: [2 x (X tile 128x20 + W tile 64x20)] = 7680 floats vs logits 128x65 = 8320
    __shared__ __align__(16) float sm[8320];
    float* xs[2] = { sm,        sm + 3840 };
    float* ws[2] = { sm + 2560, sm + 6400 };

    const int tid   = threadIdx.x;
    const int lane  = tid & 31;
    const int w     = tid >> 5;
    const int tg    = (w & 3) * 8 + (lane >> 2);  // token group 0..31 (tokens tg+32i)
    const int eg_lo = lane & 3;
    const int eg    = (w >> 2) * 4 + eg_lo;       // expert group 0..15 (experts eg*4+j)
    const int blk   = blockIdx.x;
    const float* Xblk = X + (size_t)blk * BM * HDIM;

    // ---- tile loader (cp.async, no transpose; W stored with chunk-XOR swizzle) ----
    auto load_tile = [&](int kt) {
        float* xb = xs[kt & 1];
        float* wb = ws[kt & 1];
        {   // X: 128 rows x 4 chunks(16B) = 512 chunks, 1 per thread
            int r = tid >> 2, q = tid & 3;
            cp16(smem_u32(xb + r * XST + q * 4), Xblk + (size_t)r * HDIM + kt * BK + q * 4);
        }
        if (tid < 256) {  // W: 64 rows x 4 chunks
            int r = tid >> 2, q = tid & 3;
            int p = q ^ ((r >> 2) & 3);  // swizzle: spreads rows {0,4,8,12}+b over banks
            cp16(smem_u32(wb + r * WST + p * 4), W + (size_t)r * HDIM + kt * BK + q * 4);
        }
    };

    load_tile(0);
    cp_commit();

    unsigned long long acc[4][4] = {};  // per-tile packed fp32 chains (len 8/component)
    double dacc[4][4] = {};             // exact cross-tile carry

    const int NT = HDIM / BK;  // 64 tiles
    for (int kt = 0; kt < NT; ++kt) {
        cp_wait0();
        __syncthreads();
        if (kt + 1 < NT) { load_tile(kt + 1); cp_commit(); }

        const float* xsb = xs[kt & 1];
        const float* wsb = ws[kt & 1];
        #pragma unroll
        for (int kk = 0; kk < BK / 4; ++kk) {
            const int pc = (kk ^ eg_lo) * 4;  // physical chunk (undo store swizzle)
            ulonglong2 wv[4];
            #pragma unroll
            for (int j = 0; j < 4; ++j)
                wv[j] = *(const ulonglong2*)(wsb + (eg * 4 + j) * WST + pc);
            #pragma unroll
            for (int i = 0; i < 4; ++i) {
                ulonglong2 xv = *(const ulonglong2*)(xsb + (tg + 32 * i) * XST + kk * 4);
                #pragma unroll
                for (int j = 0; j < 4; ++j) {
                    fma2(acc[i][j], xv.x, wv[j].x);
                    fma2(acc[i][j], xv.y, wv[j].y);
                }
            }
        }
        // fold short fp32 chains into exact fp64 accumulators
        #pragma unroll
        for (int i = 0; i < 4; ++i)
            #pragma unroll
            for (int j = 0; j < 4; ++j) {
                float2 f = unpack2(acc[i][j]);
                dacc[i][j] += (double)(f.x + f.y);
                acc[i][j] = 0ULL;
            }
        __syncthreads();  // all warps done reading buf kt&1 before it's overwritten
    }

    // ---- write logits to smem overlay ----
    float* lg = sm;  // [128][65]
    #pragma unroll
    for (int i = 0; i < 4; ++i)
        #pragma unroll
        for (int j = 0; j < 4; ++j)
            lg[(tg + 32 * i) * 65 + eg * 4 + j] = (float)dacc[i][j];
    __syncthreads();

    // ---- softmax + top-8 per token: warp w handles tokens [8w, 8w+8) ----
    float ls0 = 0.0f, ls1 = 0.0f;  // per-expert score sums (expert = lane, lane+32)
    int   c0  = 0,    c1  = 0;     // per-expert topk counts

    for (int t = w * 8; t < w * 8 + 8; ++t) {
        float l0 = lg[t * 65 + lane];
        float l1 = lg[t * 65 + 32 + lane];
        float m = fmaxf(l0, l1);
        #pragma unroll
        for (int off = 16; off; off >>= 1)
            m = fmaxf(m, __shfl_xor_sync(0xffffffffu, m, off));
        float s0 = expf(l0 - m), s1 = expf(l1 - m);
        float z = s0 + s1;
        #pragma unroll
        for (int off = 16; off; off >>= 1)
            z += __shfl_xor_sync(0xffffffffu, z, off);
        s0 /= z; s1 /= z;
        ls0 += s0; ls1 += s1;

        float r0 = s0, r1 = s1;
        float sumTop = 0.0f, myS = 0.0f;
        int myIdx = 0;
        #pragma unroll
        for (int r = 0; r < KTOP; ++r) {
            float v; int id;
            if (r0 >= r1) { v = r0; id = lane; }        // tie -> lower index
            else          { v = r1; id = lane + 32; }
            #pragma unroll
            for (int off = 16; off; off >>= 1) {
                float v2 = __shfl_xor_sync(0xffffffffu, v, off);
                int   i2 = __shfl_xor_sync(0xffffffffu, id, off);
                if (v2 > v || (v2 == v && i2 < id)) { v = v2; id = i2; }
            }
            sumTop += v;
            if (lane == r) { myS = v; myIdx = id; }
            if (id == lane)            { r0 = -1.0f; c0++; }
            else if (id == lane + 32)  { r1 = -1.0f; c1++; }
        }
        if (lane < KTOP) {
            size_t gt = (size_t)(blk * BM + t) * KTOP + lane;
            outIdx[gt] = (float)myIdx;
            outW[gt]   = myS / (sumTop + 1e-20f);
        }
    }

    atomicAdd(&g_esum[lane],      ls0);
    atomicAdd(&g_esum[lane + 32], ls1);
    if (c0) atomicAdd(&g_ecnt[lane],      c0);
    if (c1) atomicAdd(&g_ecnt[lane + 32], c1);
}

__global__ void fin_k(float* __restrict__ aux, int N) {
    int lane = threadIdx.x;  // 32 threads
    float p = g_esum[lane] * (float)g_ecnt[lane]
            + g_esum[lane + 32] * (float)g_ecnt[lane + 32];
    #pragma unroll
    for (int off = 16; off; off >>= 1)
        p += __shfl_xor_sync(0xffffffffu, p, off);
    if (lane == 0) {
        // aux = ALPHA * E * sum(esum*cnt) / (N * (N*K))
        float denom = (float)N * (float)(N * KTOP);
        *aux = 0.01f * 64.0f * p / denom;
    }
}

extern "C" void kernel_launch(void* const* d_in, const int* in_sizes, int n_in,
                              void* d_out, int out_size) {
    const float* X = (const float*)d_in[0];   // hidden_states [4,8192,1024] f32
    const float* W = (const float*)d_in[1];   // weight [64,1024] f32
    float* out = (float*)d_out;               // [idx (N*8) | weight (N*8) | aux (1)]
    int N = in_sizes[0] / HDIM;               // 32768

    zero_k<<<1, 64>>>();
    gate_k<<<N / BM, NTHREADS>>>(X, W, out, out + (size_t)N * KTOP, N);
    fin_k<<<1, 32>>>(out + (size_t)2 * N * KTOP, N);
}

// round 3
// speedup vs baseline: 2.9711x; 2.9711x over previous
#include <cuda_runtime.h>
#include <cstdint>

#define HDIM 1024
#define NEXP 64
#define KTOP 8
#define BM   128
#define BK   16
#define NT   (HDIM / BK)     // 64 k-tiles
#define XST  20              // smem row stride (floats), conflict-free (banks 20r mod 32)
#define STG_X (BM * XST)     // 2560
#define STG_W (NEXP * XST)   // 1280
#define STG   (STG_X + STG_W) // 3840 floats per pipeline stage
#define NTHREADS 512

__device__ float g_esum[NEXP];  // zero-initialized at module load; fin_k self-resets
__device__ int   g_ecnt[NEXP];

__device__ __forceinline__ unsigned smem_u32(const void* p) {
    return (unsigned)__cvta_generic_to_shared(p);
}
__device__ __forceinline__ void cp16(unsigned dst, const void* src) {
    asm volatile("cp.async.cg.shared.global [%0], [%1], 16;\n" :: "r"(dst), "l"(src));
}
__device__ __forceinline__ void cp_commit() { asm volatile("cp.async.commit_group;\n"); }
__device__ __forceinline__ void cp_wait1()  { asm volatile("cp.async.wait_group 1;\n" ::: "memory"); }

// packed f32x2 FMA: d = a*b + d (componentwise)
__device__ __forceinline__ void fma2(unsigned long long& d,
                                     unsigned long long a,
                                     unsigned long long b) {
    asm("fma.rn.f32x2 %0, %1, %2, %3;" : "=l"(d) : "l"(a), "l"(b), "l"(d));
}
__device__ __forceinline__ float2 unpack2(unsigned long long v) {
    float2 f;
    asm("mov.b64 {%0, %1}, %2;" : "=f"(f.x), "=f"(f.y) : "l"(v));
    return f;
}

__global__ __launch_bounds__(NTHREADS, 1)
void gate_k(const float* __restrict__ X, const float* __restrict__ W,
            float* __restrict__ outIdx, float* __restrict__ outW, int N) {
    // 3 pipeline stages (46KB); logits [128][65]=8320 + reduction 2048 overlay after loop
    __shared__ __align__(16) float sm[3 * STG];

    const int tid  = threadIdx.x;
    const int lane = tid & 31;
    const int w    = tid >> 5;
    const int tg   = (w & 3) * 8 + (lane >> 2);   // token group 0..31 -> tokens tg+32i
    const int eg   = (w >> 2) * 4 + (lane & 3);   // expert group 0..15 -> experts eg*4+j
    const float* Xblk = X + (size_t)blockIdx.x * BM * HDIM;

    const int xr = tid >> 2, xq = tid & 3;         // X: 128 rows x 4 chunks, 1 cp/thread
    const int wr = (tid & 255) >> 2;               // W: 64 rows x 4 chunks, tid<256

    auto load_tile = [&](int kt) {
        float* base = sm + (kt % 3) * STG;
        cp16(smem_u32(base + xr * XST + xq * 4),
             Xblk + (size_t)xr * HDIM + kt * BK + xq * 4);
        if (tid < 256)
            cp16(smem_u32(base + STG_X + wr * XST + xq * 4),
                 W + (size_t)wr * HDIM + kt * BK + xq * 4);
        cp_commit();
    };

    load_tile(0);
    load_tile(1);

    unsigned long long acc[4][4] = {};   // packed per-tile chains (8 terms/component)
    float ksum[4][4] = {};               // Kahan master sums
    float kcmp[4][4] = {};               // Kahan compensations

    for (int kt = 0; kt < NT; ++kt) {
        cp_wait1();          // stage kt fully landed (own groups), then barrier for all threads
        __syncthreads();     // also: everyone done computing kt-1 -> safe to overwrite buf (kt+2)%3
        if (kt + 2 < NT) load_tile(kt + 2); else cp_commit();

        const float* xsb = sm + (kt % 3) * STG;
        const float* wsb = xsb + STG_X;
        #pragma unroll
        for (int kk = 0; kk < BK / 4; ++kk) {
            ulonglong2 wv[4];
            #pragma unroll
            for (int j = 0; j < 4; ++j)
                wv[j] = *(const ulonglong2*)(wsb + (eg * 4 + j) * XST + kk * 4);
            #pragma unroll
            for (int i = 0; i < 4; ++i) {
                ulonglong2 xv = *(const ulonglong2*)(xsb + (tg + 32 * i) * XST + kk * 4);
                #pragma unroll
                for (int j = 0; j < 4; ++j) {
                    fma2(acc[i][j], xv.x, wv[j].x);
                    fma2(acc[i][j], xv.y, wv[j].y);
                }
            }
        }
        // Kahan-fold the short fp32 chains into master sums (no fp64 anywhere)
        #pragma unroll
        for (int i = 0; i < 4; ++i)
            #pragma unroll
            for (int j = 0; j < 4; ++j) {
                float2 f = unpack2(acc[i][j]);
                float t = f.x + f.y;
                float y = t - kcmp[i][j];
                float s = ksum[i][j] + y;
                kcmp[i][j] = (s - ksum[i][j]) - y;
                ksum[i][j] = s;
                acc[i][j] = 0ULL;
            }
    }
    __syncthreads();

    // ---- write logits to smem overlay [128][65] ----
    float* lg = sm;
    #pragma unroll
    for (int i = 0; i < 4; ++i)
        #pragma unroll
        for (int j = 0; j < 4; ++j)
            lg[(tg + 32 * i) * 65 + eg * 4 + j] = ksum[i][j];
    __syncthreads();

    // ---- softmax + top-8 per token: warp w handles tokens [8w, 8w+8) ----
    float ls0 = 0.0f, ls1 = 0.0f;  // per-expert score sums (expert = lane, lane+32)
    int   c0  = 0,    c1  = 0;

    for (int t = w * 8; t < w * 8 + 8; ++t) {
        float l0 = lg[t * 65 + lane];
        float l1 = lg[t * 65 + 32 + lane];
        float m = fmaxf(l0, l1);
        #pragma unroll
        for (int off = 16; off; off >>= 1)
            m = fmaxf(m, __shfl_xor_sync(0xffffffffu, m, off));
        float s0 = expf(l0 - m), s1 = expf(l1 - m);
        float z = s0 + s1;
        #pragma unroll
        for (int off = 16; off; off >>= 1)
            z += __shfl_xor_sync(0xffffffffu, z, off);
        s0 /= z; s1 /= z;
        ls0 += s0; ls1 += s1;

        float r0 = s0, r1 = s1;
        float sumTop = 0.0f, myS = 0.0f;
        int myIdx = 0;
        #pragma unroll
        for (int r = 0; r < KTOP; ++r) {
            float v; int id;
            if (r0 >= r1) { v = r0; id = lane; }       // tie -> lower index
            else          { v = r1; id = lane + 32; }
            #pragma unroll
            for (int off = 16; off; off >>= 1) {
                float v2 = __shfl_xor_sync(0xffffffffu, v, off);
                int   i2 = __shfl_xor_sync(0xffffffffu, id, off);
                if (v2 > v || (v2 == v && i2 < id)) { v = v2; id = i2; }
            }
            sumTop += v;
            if (lane == r) { myS = v; myIdx = id; }
            if (id == lane)           { r0 = -1.0f; c0++; }
            else if (id == lane + 32) { r1 = -1.0f; c1++; }
        }
        if (lane < KTOP) {
            size_t gt = (size_t)(blockIdx.x * BM + t) * KTOP + lane;
            outIdx[gt] = (float)myIdx;
            outW[gt]   = myS / (sumTop + 1e-20f);
        }
    }

    // ---- CTA-level reduction before global atomics (region above logits) ----
    float* redS = sm + 8320;          // [16][64]
    float* redC = sm + 8320 + 1024;   // [16][64]
    redS[w * 64 + lane]      = ls0;
    redS[w * 64 + lane + 32] = ls1;
    redC[w * 64 + lane]      = (float)c0;
    redC[w * 64 + lane + 32] = (float)c1;
    __syncthreads();
    if (tid < NEXP) {
        float es = 0.0f, ec = 0.0f;
        #pragma unroll
        for (int ww = 0; ww < 16; ++ww) {
            es += redS[ww * 64 + tid];
            ec += redC[ww * 64 + tid];
        }
        atomicAdd(&g_esum[tid], es);
        if (ec != 0.0f) atomicAdd(&g_ecnt[tid], (int)ec);
    }
}

__global__ void fin_k(float* __restrict__ aux, int N) {
    int lane = threadIdx.x;  // 32 threads
    float p = g_esum[lane] * (float)g_ecnt[lane]
            + g_esum[lane + 32] * (float)g_ecnt[lane + 32];
    // self-reset so the next graph replay starts from zero (replaces zero_k)
    g_esum[lane] = 0.0f;       g_esum[lane + 32] = 0.0f;
    g_ecnt[lane] = 0;          g_ecnt[lane + 32] = 0;
    #pragma unroll
    for (int off = 16; off; off >>= 1)
        p += __shfl_xor_sync(0xffffffffu, p, off);
    if (lane == 0) {
        // aux = ALPHA * E * sum(esum*cnt) / (N * (N*K))
        float denom = (float)N * (float)(N * KTOP);
        *aux = 0.01f * 64.0f * p / denom;
    }
}

extern "C" void kernel_launch(void* const* d_in, const int* in_sizes, int n_in,
                              void* d_out, int out_size) {
    const float* X = (const float*)d_in[0];   // hidden_states [4,8192,1024] f32
    const float* W = (const float*)d_in[1];   // weight [64,1024] f32
    float* out = (float*)d_out;               // [idx (N*8) | weight (N*8) | aux (1)]
    int N = in_sizes[0] / HDIM;               // 32768

    gate_k<<<N / BM, NTHREADS>>>(X, W, out, out + (size_t)N * KTOP, N);
    fin_k<<<1, 32>>>(out + (size_t)2 * N * KTOP, N);
}

// round 4
// speedup vs baseline: 4.1079x; 1.3827x over previous
#include <cuda_runtime.h>
#include <cstdint>

#define HDIM 1024
#define NEXP 64
#define KTOP 8
#define BM   128
#define BK   16
#define NT   (HDIM / BK)      // 64 k-tiles
#define XST  20               // smem row stride (floats)
#define STG_X (BM * XST)      // 2560
#define STG_W (NEXP * XST)    // 1280
#define STG   (STG_X + STG_W) // 3840 floats per pipeline stage
#define NTHREADS 512

__device__ float    g_esum[NEXP];   // zero-init at load; last CTA self-resets
__device__ int      g_ecnt[NEXP];
__device__ unsigned g_done = 0;

__device__ __forceinline__ unsigned smem_u32(const void* p) {
    return (unsigned)__cvta_generic_to_shared(p);
}
__device__ __forceinline__ void cp16(unsigned dst, const void* src) {
    asm volatile("cp.async.cg.shared.global [%0], [%1], 16;\n" :: "r"(dst), "l"(src));
}
__device__ __forceinline__ void cp_commit() { asm volatile("cp.async.commit_group;\n"); }
__device__ __forceinline__ void cp_wait1()  { asm volatile("cp.async.wait_group 1;\n" ::: "memory"); }

// packed f32x2 FMA: d = a*b + d (componentwise)
__device__ __forceinline__ void fma2(unsigned long long& d,
                                     unsigned long long a,
                                     unsigned long long b) {
    asm("fma.rn.f32x2 %0, %1, %2, %3;" : "=l"(d) : "l"(a), "l"(b), "l"(d));
}
__device__ __forceinline__ float2 unpack2(unsigned long long v) {
    float2 f;
    asm("mov.b64 {%0, %1}, %2;" : "=f"(f.x), "=f"(f.y) : "l"(v));
    return f;
}

__global__ __launch_bounds__(NTHREADS, 1)
void gate_k(const float* __restrict__ X, const float* __restrict__ W,
            float* __restrict__ outIdx, float* __restrict__ outW,
            float* __restrict__ outAux, int N) {
    // 3 pipeline stages (45KB); logits [128][65] + reductions overlay after the loop
    __shared__ __align__(16) float sm[3 * STG];
    __shared__ unsigned isLast;

    const int tid  = threadIdx.x;
    const int lane = tid & 31;
    const int w    = tid >> 5;
    const int tg   = (w & 3) * 8 + (lane >> 2);   // token group 0..31 -> tokens tg+32i
    const int eg   = (w >> 2) * 4 + (lane & 3);   // expert group 0..15 -> experts eg*4+j
    const int esw  = lane & 3;                    // W chunk-XOR swizzle key (== eg & 3)
    const float* Xblk = X + (size_t)blockIdx.x * BM * HDIM;

    const int xr = tid >> 2, xq = tid & 3;        // X: 128 rows x 4 chunks, 1 cp/thread
    const int wr = (tid & 255) >> 2;              // W: 64 rows x 4 chunks, tid<256
    const int wp = xq ^ ((wr >> 2) & 3);          // store-side chunk swizzle

    auto load_tile = [&](int kt) {
        float* base = sm + (kt % 3) * STG;
        cp16(smem_u32(base + xr * XST + xq * 4),
             Xblk + (size_t)xr * HDIM + kt * BK + xq * 4);
        if (tid < 256)
            cp16(smem_u32(base + STG_X + wr * XST + wp * 4),
                 W + (size_t)wr * HDIM + kt * BK + xq * 4);
        cp_commit();
    };

    load_tile(0);
    load_tile(1);

    unsigned long long acc[4][4] = {};   // packed chains: 16 terms/component per fold
    float ksum[4][4] = {};               // Kahan master sums
    float kcmp[4][4] = {};               // Kahan compensations

    #pragma unroll 2
    for (int kt = 0; kt < NT; ++kt) {
        cp_wait1();          // stage kt landed
        __syncthreads();     // + everyone done with buf being overwritten next
        if (kt + 2 < NT) load_tile(kt + 2); else cp_commit();

        const float* xsb = sm + (kt % 3) * STG;
        const float* wsb = xsb + STG_X;
        #pragma unroll
        for (int kk = 0; kk < BK / 4; ++kk) {
            const int pc = (kk ^ esw) * 4;   // undo store swizzle -> conflict-free
            ulonglong2 wv[4];
            #pragma unroll
            for (int j = 0; j < 4; ++j)
                wv[j] = *(const ulonglong2*)(wsb + (eg * 4 + j) * XST + pc);
            #pragma unroll
            for (int i = 0; i < 4; ++i) {
                ulonglong2 xv = *(const ulonglong2*)(xsb + (tg + 32 * i) * XST + kk * 4);
                #pragma unroll
                for (int j = 0; j < 4; ++j) {
                    fma2(acc[i][j], xv.x, wv[j].x);
                    fma2(acc[i][j], xv.y, wv[j].y);
                }
            }
        }
        if (kt & 1) {  // Kahan-fold short fp32 chains every 2 tiles
            #pragma unroll
            for (int i = 0; i < 4; ++i)
                #pragma unroll
                for (int j = 0; j < 4; ++j) {
                    float2 f = unpack2(acc[i][j]);
                    float t = f.x + f.y;
                    float y = t - kcmp[i][j];
                    float s = ksum[i][j] + y;
                    kcmp[i][j] = (s - ksum[i][j]) - y;
                    ksum[i][j] = s;
                    acc[i][j] = 0ULL;
                }
        }
    }
    __syncthreads();

    // ---- write logits to smem overlay [128][65] ----
    float* lg = sm;
    #pragma unroll
    for (int i = 0; i < 4; ++i)
        #pragma unroll
        for (int j = 0; j < 4; ++j)
            lg[(tg + 32 * i) * 65 + eg * 4 + j] = ksum[i][j];
    __syncthreads();

    // ---- softmax + top-8 per token: warp w handles tokens [8w, 8w+8) ----
    float ls0 = 0.0f, ls1 = 0.0f;  // per-expert score sums (expert = lane, lane+32)
    int   c0  = 0,    c1  = 0;

    for (int t = w * 8; t < w * 8 + 8; ++t) {
        float l0 = lg[t * 65 + lane];
        float l1 = lg[t * 65 + 32 + lane];
        float m = fmaxf(l0, l1);
        #pragma unroll
        for (int off = 16; off; off >>= 1)
            m = fmaxf(m, __shfl_xor_sync(0xffffffffu, m, off));
        float s0 = expf(l0 - m), s1 = expf(l1 - m);
        float z = s0 + s1;
        #pragma unroll
        for (int off = 16; off; off >>= 1)
            z += __shfl_xor_sync(0xffffffffu, z, off);
        s0 /= z; s1 /= z;
        ls0 += s0; ls1 += s1;

        float r0 = s0, r1 = s1;
        float sumTop = 0.0f, myS = 0.0f;
        int myIdx = 0;
        #pragma unroll
        for (int r = 0; r < KTOP; ++r) {
            float v; int id;
            if (r0 >= r1) { v = r0; id = lane; }       // tie -> lower index
            else          { v = r1; id = lane + 32; }
            #pragma unroll
            for (int off = 16; off; off >>= 1) {
                float v2 = __shfl_xor_sync(0xffffffffu, v, off);
                int   i2 = __shfl_xor_sync(0xffffffffu, id, off);
                if (v2 > v || (v2 == v && i2 < id)) { v = v2; id = i2; }
            }
            sumTop += v;
            if (lane == r) { myS = v; myIdx = id; }
            if (id == lane)           { r0 = -1.0f; c0++; }
            else if (id == lane + 32) { r1 = -1.0f; c1++; }
        }
        if (lane < KTOP) {
            size_t gt = (size_t)(blockIdx.x * BM + t) * KTOP + lane;
            outIdx[gt] = (float)myIdx;
            outW[gt]   = myS / (sumTop + 1e-20f);
        }
    }

    // ---- CTA-level reduction, then 64 global atomics ----
    float* redS = sm;          // [16][64]  (logits no longer needed)
    float* redC = sm + 1024;   // [16][64]
    redS[w * 64 + lane]      = ls0;
    redS[w * 64 + lane + 32] = ls1;
    redC[w * 64 + lane]      = (float)c0;
    redC[w * 64 + lane + 32] = (float)c1;
    __syncthreads();
    if (tid < NEXP) {
        float es = 0.0f, ec = 0.0f;
        #pragma unroll
        for (int ww = 0; ww < 16; ++ww) {
            es += redS[ww * 64 + tid];
            ec += redC[ww * 64 + tid];
        }
        atomicAdd(&g_esum[tid], es);
        if (ec != 0.0f) atomicAdd(&g_ecnt[tid], (int)ec);
    }

    // ---- last-CTA finalize (replaces fin_k launch) ----
    __threadfence();
    __syncthreads();
    if (tid == 0)
        isLast = (atomicAdd(&g_done, 1u) == gridDim.x - 1) ? 1u : 0u;
    __syncthreads();
    if (isLast && tid < 32) {
        float p = g_esum[tid] * (float)g_ecnt[tid]
                + g_esum[tid + 32] * (float)g_ecnt[tid + 32];
        // self-reset for the next graph replay
        g_esum[tid] = 0.0f;  g_esum[tid + 32] = 0.0f;
        g_ecnt[tid] = 0;     g_ecnt[tid + 32] = 0;
        #pragma unroll
        for (int off = 16; off; off >>= 1)
            p += __shfl_xor_sync(0xffffffffu, p, off);
        if (tid == 0) {
            g_done = 0;
            float denom = (float)N * (float)(N * KTOP);
            *outAux = 0.01f * 64.0f * p / denom;   // ALPHA * E * sum / (N * N*K)
        }
    }
}

extern "C" void kernel_launch(void* const* d_in, const int* in_sizes, int n_in,
                              void* d_out, int out_size) {
    const float* X = (const float*)d_in[0];   // hidden_states [4,8192,1024] f32
    const float* W = (const float*)d_in[1];   // weight [64,1024] f32
    float* out = (float*)d_out;               // [idx (N*8) | weight (N*8) | aux (1)]
    int N = in_sizes[0] / HDIM;               // 32768

    gate_k<<<N / BM, NTHREADS>>>(X, W, out, out + (size_t)N * KTOP,
                                 out + (size_t)2 * N * KTOP, N);
}

// round 5
// speedup vs baseline: 4.1213x; 1.0033x over previous
#include <cuda_runtime.h>
#include <cstdint>

#define HDIM 1024
#define NEXP 64
#define KTOP 8
#define BM   128
#define BK   16
#define NT   (HDIM / BK)      // 64 k-tiles
#define XST  20               // smem row stride (floats)
#define STG_X (BM * XST)      // 2560
#define STG_W (NEXP * XST)    // 1280
#define STG   (STG_X + STG_W) // 3840 floats per pipeline stage
#define NTHREADS 512

__device__ float    g_esum[NEXP];   // zero-init at load; last CTA self-resets
__device__ int      g_ecnt[NEXP];
__device__ unsigned g_done = 0;

__device__ __forceinline__ unsigned smem_u32(const void* p) {
    return (unsigned)__cvta_generic_to_shared(p);
}
__device__ __forceinline__ void cp16(unsigned dst, const void* src) {
    asm volatile("cp.async.cg.shared.global [%0], [%1], 16;\n" :: "r"(dst), "l"(src));
}
__device__ __forceinline__ void cp_commit() { asm volatile("cp.async.commit_group;\n"); }
__device__ __forceinline__ void cp_wait1()  { asm volatile("cp.async.wait_group 1;\n" ::: "memory"); }

// packed f32x2 FMA: d = a*b + d (componentwise)
__device__ __forceinline__ void fma2(unsigned long long& d,
                                     unsigned long long a,
                                     unsigned long long b) {
    asm("fma.rn.f32x2 %0, %1, %2, %3;" : "=l"(d) : "l"(a), "l"(b), "l"(d));
}
__device__ __forceinline__ float2 unpack2(unsigned long long v) {
    float2 f;
    asm("mov.b64 {%0, %1}, %2;" : "=f"(f.x), "=f"(f.y) : "l"(v));
    return f;
}

__global__ __launch_bounds__(NTHREADS, 1)
void gate_k(const float* __restrict__ X, const float* __restrict__ W,
            float* __restrict__ outIdx, float* __restrict__ outW,
            float* __restrict__ outAux, int N) {
    // 3 pipeline stages (45KB); logits [128][65] + reductions overlay after the loop
    __shared__ __align__(16) float sm[3 * STG];
    __shared__ unsigned isLast;

    const int tid  = threadIdx.x;
    const int lane = tid & 31;
    const int w    = tid >> 5;
    const int tg   = (w & 3) * 8 + (lane >> 2);   // token group 0..31 -> tokens tg+32i
    const int eg   = (w >> 2) * 4 + (lane & 3);   // expert group 0..15 -> experts eg*4+j
    const int esw  = lane & 3;                    // W chunk-XOR swizzle key (== eg & 3)
    const float* Xblk = X + (size_t)blockIdx.x * BM * HDIM;

    const int xr = tid >> 2, xq = tid & 3;        // X: 128 rows x 4 chunks, 1 cp/thread
    const int wr = (tid & 255) >> 2;              // W: 64 rows x 4 chunks, tid<256
    const int wp = xq ^ ((wr >> 2) & 3);          // store-side chunk swizzle

    auto load_tile = [&](int kt) {
        float* base = sm + (kt % 3) * STG;
        cp16(smem_u32(base + xr * XST + xq * 4),
             Xblk + (size_t)xr * HDIM + kt * BK + xq * 4);
        if (tid < 256)
            cp16(smem_u32(base + STG_X + wr * XST + wp * 4),
                 W + (size_t)wr * HDIM + kt * BK + xq * 4);
        cp_commit();
    };

    load_tile(0);
    load_tile(1);

    unsigned long long acc[4][4] = {};   // packed chains: 16 terms/component per fold
    float ksum[4][4] = {};               // Kahan master sums
    float kcmp[4][4] = {};               // Kahan compensations

    #pragma unroll 2
    for (int kt = 0; kt < NT; ++kt) {
        cp_wait1();          // stage kt landed
        __syncthreads();     // + everyone done with buf being overwritten next
        if (kt + 2 < NT) load_tile(kt + 2); else cp_commit();

        const float* xsb = sm + (kt % 3) * STG;
        const float* wsb = xsb + STG_X;
        #pragma unroll
        for (int kk = 0; kk < BK / 4; ++kk) {
            const int pc = (kk ^ esw) * 4;   // undo store swizzle -> conflict-free
            ulonglong2 wv[4];
            #pragma unroll
            for (int j = 0; j < 4; ++j)
                wv[j] = *(const ulonglong2*)(wsb + (eg * 4 + j) * XST + pc);
            #pragma unroll
            for (int i = 0; i < 4; ++i) {
                ulonglong2 xv = *(const ulonglong2*)(xsb + (tg + 32 * i) * XST + kk * 4);
                #pragma unroll
                for (int j = 0; j < 4; ++j) {
                    fma2(acc[i][j], xv.x, wv[j].x);
                    fma2(acc[i][j], xv.y, wv[j].y);
                }
            }
        }
        if (kt & 1) {  // Kahan-fold short fp32 chains every 2 tiles
            #pragma unroll
            for (int i = 0; i < 4; ++i)
                #pragma unroll
                for (int j = 0; j < 4; ++j) {
                    float2 f = unpack2(acc[i][j]);
                    float t = f.x + f.y;
                    float y = t - kcmp[i][j];
                    float s = ksum[i][j] + y;
                    kcmp[i][j] = (s - ksum[i][j]) - y;
                    ksum[i][j] = s;
                    acc[i][j] = 0ULL;
                }
        }
    }
    __syncthreads();

    // ---- write logits to smem overlay [128][65] ----
    float* lg = sm;
    #pragma unroll
    for (int i = 0; i < 4; ++i)
        #pragma unroll
        for (int j = 0; j < 4; ++j)
            lg[(tg + 32 * i) * 65 + eg * 4 + j] = ksum[i][j];
    __syncthreads();

    // ---- softmax + top-8 per token: warp w handles tokens [8w, 8w+8) ----
    float ls0 = 0.0f, ls1 = 0.0f;  // per-expert score sums (expert = lane, lane+32)
    int   c0  = 0,    c1  = 0;

    for (int t = w * 8; t < w * 8 + 8; ++t) {
        float l0 = lg[t * 65 + lane];
        float l1 = lg[t * 65 + 32 + lane];
        float m = fmaxf(l0, l1);
        #pragma unroll
        for (int off = 16; off; off >>= 1)
            m = fmaxf(m, __shfl_xor_sync(0xffffffffu, m, off));
        float s0 = expf(l0 - m), s1 = expf(l1 - m);
        float z = s0 + s1;
        #pragma unroll
        for (int off = 16; off; off >>= 1)
            z += __shfl_xor_sync(0xffffffffu, z, off);
        s0 /= z; s1 /= z;
        ls0 += s0; ls1 += s1;

        float r0 = s0, r1 = s1;
        float sumTop = 0.0f, myS = 0.0f;
        int myIdx = 0;
        #pragma unroll
        for (int r = 0; r < KTOP; ++r) {
            float v; int id;
            if (r0 >= r1) { v = r0; id = lane; }       // tie -> lower index
            else          { v = r1; id = lane + 32; }
            #pragma unroll
            for (int off = 16; off; off >>= 1) {
                float v2 = __shfl_xor_sync(0xffffffffu, v, off);
                int   i2 = __shfl_xor_sync(0xffffffffu, id, off);
                if (v2 > v || (v2 == v && i2 < id)) { v = v2; id = i2; }
            }
            sumTop += v;
            if (lane == r) { myS = v; myIdx = id; }
            if (id == lane)           { r0 = -1.0f; c0++; }
            else if (id == lane + 32) { r1 = -1.0f; c1++; }
        }
        if (lane < KTOP) {
            size_t gt = (size_t)(blockIdx.x * BM + t) * KTOP + lane;
            outIdx[gt] = (float)myIdx;
            outW[gt]   = myS / (sumTop + 1e-20f);
        }
    }

    // ---- CTA-level reduction, then 64 global atomics ----
    float* redS = sm;          // [16][64]  (logits no longer needed)
    float* redC = sm + 1024;   // [16][64]
    redS[w * 64 + lane]      = ls0;
    redS[w * 64 + lane + 32] = ls1;
    redC[w * 64 + lane]      = (float)c0;
    redC[w * 64 + lane + 32] = (float)c1;
    __syncthreads();
    if (tid < NEXP) {
        float es = 0.0f, ec = 0.0f;
        #pragma unroll
        for (int ww = 0; ww < 16; ++ww) {
            es += redS[ww * 64 + tid];
            ec += redC[ww * 64 + tid];
        }
        atomicAdd(&g_esum[tid], es);
        if (ec != 0.0f) atomicAdd(&g_ecnt[tid], (int)ec);
    }

    // ---- last-CTA finalize (replaces fin_k launch) ----
    __threadfence();
    __syncthreads();
    if (tid == 0)
        isLast = (atomicAdd(&g_done, 1u) == gridDim.x - 1) ? 1u : 0u;
    __syncthreads();
    if (isLast && tid < 32) {
        float p = g_esum[tid] * (float)g_ecnt[tid]
                + g_esum[tid + 32] * (float)g_ecnt[tid + 32];
        // self-reset for the next graph replay
        g_esum[tid] = 0.0f;  g_esum[tid + 32] = 0.0f;
        g_ecnt[tid] = 0;     g_ecnt[tid + 32] = 0;
        #pragma unroll
        for (int off = 16; off; off >>= 1)
            p += __shfl_xor_sync(0xffffffffu, p, off);
        if (tid == 0) {
            g_done = 0;
            float denom = (float)N * (float)(N * KTOP);
            *outAux = 0.01f * 64.0f * p / denom;   // ALPHA * E * sum / (N * N*K)
        }
    }
}

extern "C" void kernel_launch(void* const* d_in, const int* in_sizes, int n_in,
                              void* d_out, int out_size) {
    const float* X = (const float*)d_in[0];   // hidden_states [4,8192,1024] f32
    const float* W = (const float*)d_in[1];   // weight [64,1024] f32
    float* out = (float*)d_out;               // [idx (N*8) | weight (N*8) | aux (1)]
    int N = in_sizes[0] / HDIM;               // 32768

    gate_k<<<N / BM, NTHREADS>>>(X, W, out, out + (size_t)N * KTOP,
                                 out + (size_t)2 * N * KTOP, N);
}

// round 8
// speedup vs baseline: 5.9326x; 1.4395x over previous
#include <cuda_runtime.h>
#include <cuda_bf16.h>
#include <cstdint>

#define HDIM 1024
#define NEXP 64
#define KTOP 8
#define BM   128
#define KC   64
#define NCHUNK 16
#define NTHREADS 512

#define A_STAGE 49152              // 3 splits x 8 mt x 4 kt x 32 lanes x 16B
#define B_STAGE 24576              // 3 splits x 4 kt x 2 nh x 2 ntp x 32 x 16B
#define B_BASE  (2 * A_STAGE)      // A double-buffered
#define SMEM_TOTAL (B_BASE + 4 * B_STAGE)   // 196608 B

__device__ unsigned short g_wp[3 * 64 * 2 * 2 * 32 * 8];  // W splits, frag-permuted
__device__ float    g_esum[NEXP];
__device__ int      g_ecnt[NEXP];
__device__ unsigned g_done = 0;

__device__ __forceinline__ unsigned smem_u32(const void* p) {
    return (unsigned)__cvta_generic_to_shared(p);
}
__device__ __forceinline__ void cp16(unsigned dst, const void* src) {
    asm volatile("cp.async.cg.shared.global [%0], [%1], 16;\n" :: "r"(dst), "l"(src));
}
__device__ __forceinline__ void cp_commit() { asm volatile("cp.async.commit_group;\n"); }
__device__ __forceinline__ void cp_wait1()  { asm volatile("cp.async.wait_group 1;\n" ::: "memory"); }

__device__ __forceinline__ uint32_t cvt_bf16x2(float hi, float lo) {  // hi -> upper half
    uint32_t d; asm("cvt.rn.bf16x2.f32 %0, %1, %2;" : "=r"(d) : "f"(hi), "f"(lo)); return d;
}
__device__ __forceinline__ float ubflo(uint32_t u) { return __uint_as_float(u << 16); }
__device__ __forceinline__ float ubfhi(uint32_t u) { return __uint_as_float(u & 0xFFFF0000u); }

__device__ __forceinline__ void lds128(uint32_t* r, unsigned a) {
    asm volatile("ld.shared.v4.u32 {%0,%1,%2,%3}, [%4];"
                 : "=r"(r[0]), "=r"(r[1]), "=r"(r[2]), "=r"(r[3]) : "r"(a));
}
__device__ __forceinline__ void sts32(unsigned a, uint32_t v) {
    asm volatile("st.shared.u32 [%0], %1;" :: "r"(a), "r"(v));
}
// D(16x8,f32) += A(16x16,bf16 row) x B(16x8,bf16 col)
__device__ __forceinline__ void mma16816(float* d, const uint32_t* a, const uint32_t* b) {
    asm volatile("mma.sync.aligned.m16n8k16.row.col.f32.bf16.bf16.f32 "
                 "{%0,%1,%2,%3}, {%4,%5,%6,%7}, {%8,%9}, {%0,%1,%2,%3};"
                 : "+f"(d[0]), "+f"(d[1]), "+f"(d[2]), "+f"(d[3])
                 : "r"(a[0]), "r"(a[1]), "r"(a[2]), "r"(a[3]), "r"(b[0]), "r"(b[1]));
}

// Split W (rounded 3-way) and store in B-fragment-permuted layout.
__global__ void wsplit_k(const float* __restrict__ W) {
    int i = blockIdx.x * 256 + threadIdx.x;   // i = n*1024 + k
    int n = i >> 10, k = i & 1023;
    float x = W[i];
    __nv_bfloat16 bh = __float2bfloat16_rn(x);
    float r1 = x - __bfloat162float(bh);
    __nv_bfloat16 bm = __float2bfloat16_rn(r1);
    float r2 = r1 - __bfloat162float(bm);
    __nv_bfloat16 bl = __float2bfloat16_rn(r2);
    unsigned short hv[3];
    hv[0] = *reinterpret_cast<unsigned short*>(&bh);
    hv[1] = *reinterpret_cast<unsigned short*>(&bm);
    hv[2] = *reinterpret_cast<unsigned short*>(&bl);

    int kt = k >> 4, kl = k & 15;
    int lane = ((n & 7) << 2) | ((kl >> 1) & 3);
    int reg  = (kl >> 3) & 1;
    int nh   = n >> 5, ntp = (n >> 4) & 1;
    int w4   = ((n >> 3) & 1) * 2 + reg;
    #pragma unroll
    for (int s = 0; s < 3; ++s) {
        size_t off = ((((size_t)s * 64 + kt) * 2 + nh) * 2 + ntp) * 32 + lane;  // 16B units
        g_wp[off * 8 + w4 * 2 + (kl & 1)] = hv[s];
    }
}

extern __shared__ char dynsm[];

__global__ __launch_bounds__(NTHREADS, 1)
void gate_k(const float* __restrict__ X,
            float* __restrict__ outIdx, float* __restrict__ outW,
            float* __restrict__ outAux, int N) {
    const int tid  = threadIdx.x;
    const int lane = tid & 31;
    const int w    = tid >> 5;
    const int mt   = w >> 1;   // m-tile (16 tokens)
    const int nh   = w & 1;    // n-half (32 experts)
    const float* Xblk = X + (size_t)blockIdx.x * BM * HDIM;
    const unsigned sbu = smem_u32(dynsm);

    // converter mapping: 4 rows (rbase+32i), one float4 (4 k) each
    const int rbase = tid >> 4;
    const int cq    = tid & 15;
    const int ckt   = cq >> 2;          // k-tile within chunk
    const int kp0   = (cq & 3) * 2;     // even k-pair within tile

    auto loadB = [&](int c) {
        #pragma unroll
        for (int t = 0; t < 3; ++t) {
            int j = tid + t * 512;
            int s = j >> 9, rem = j & 511;
            cp16(sbu + B_BASE + (c & 3) * B_STAGE + (unsigned)(s * 512 + rem) * 16,
                 (const char*)g_wp + (((size_t)s * 64 + c * 4) * 128 + rem) * 16);
        }
        cp_commit();
    };

    auto convertStore = [&](const float4* xr, int st) {
        unsigned aB = sbu + st * A_STAGE;
        #pragma unroll
        for (int i = 0; i < 4; ++i) {
            int rr  = rbase + 32 * i;
            int mtr = rr >> 4;
            int r8  = (rr >> 3) & 1;
            unsigned l0 = ((rr & 7) << 2) | (kp0 & 3);
            unsigned l1 = ((rr & 7) << 2) | ((kp0 + 1) & 3);
            unsigned wd = (kp0 >> 2) * 2 + r8;
            float4 xf = xr[i];
            uint32_t h01 = cvt_bf16x2(xf.y, xf.x);
            uint32_t h23 = cvt_bf16x2(xf.w, xf.z);
            float r1x = xf.x - ubflo(h01), r1y = xf.y - ubfhi(h01);
            float r1z = xf.z - ubflo(h23), r1w = xf.w - ubfhi(h23);
            uint32_t m01 = cvt_bf16x2(r1y, r1x), m23 = cvt_bf16x2(r1w, r1z);
            float r2x = r1x - ubflo(m01), r2y = r1y - ubfhi(m01);
            float r2z = r1z - ubflo(m23), r2w = r1w - ubfhi(m23);
            uint32_t q01 = cvt_bf16x2(r2y, r2x), q23 = cvt_bf16x2(r2w, r2z);
            unsigned base = aB + (unsigned)((mtr * 4 + ckt) * 32) * 16 + wd * 4;
            sts32(base + l0 * 16, h01);
            sts32(base + l1 * 16, h23);
            sts32(base + 16384u + l0 * 16, m01);
            sts32(base + 16384u + l1 * 16, m23);
            sts32(base + 32768u + l0 * 16, q01);
            sts32(base + 32768u + l1 * 16, q23);
        }
    };

    // ---- prologue ----
    float4 xr[4];
    #pragma unroll
    for (int i = 0; i < 4; ++i)
        xr[i] = *((const float4*)(Xblk + (size_t)(rbase + 32 * i) * HDIM) + cq);
    loadB(0);
    loadB(1);
    convertStore(xr, 0);

    float accH[4][4] = {}, accL[4][4] = {}, kS[4][4] = {}, kC[4][4] = {};

    for (int c = 0; c < NCHUNK; ++c) {
        if (c + 1 < NCHUNK) {
            const float* xp = Xblk + (c + 1) * KC;
            #pragma unroll
            for (int i = 0; i < 4; ++i)
                xr[i] = *((const float4*)(xp + (size_t)(rbase + 32 * i) * HDIM) + cq);
        }
        cp_wait1();
        __syncthreads();

        const unsigned aB = sbu + (c & 1) * A_STAGE;
        const unsigned bB = sbu + B_BASE + (c & 3) * B_STAGE;
        #pragma unroll
        for (int kt = 0; kt < 4; ++kt) {
            uint32_t a0[4], a1[4], a2[4], bf[8];
            lds128(a0, aB + (unsigned)(((0 * 8 + mt) * 4 + kt) * 32 + lane) * 16);
            lds128(a1, aB + (unsigned)(((1 * 8 + mt) * 4 + kt) * 32 + lane) * 16);
            lds128(a2, aB + (unsigned)(((2 * 8 + mt) * 4 + kt) * 32 + lane) * 16);
            // b-split hi: hh -> accH ; mh, lh -> accL
            lds128(bf,     bB + (unsigned)(((0 * 4 + kt) * 2 + nh) * 2 + 0) * 512 + lane * 16);
            lds128(bf + 4, bB + (unsigned)(((0 * 4 + kt) * 2 + nh) * 2 + 1) * 512 + lane * 16);
            #pragma unroll
            for (int nt = 0; nt < 4; ++nt) {
                const uint32_t* b2 = bf + (nt >> 1) * 4 + (nt & 1) * 2;
                mma16816(accH[nt], a0, b2);
                mma16816(accL[nt], a1, b2);
                mma16816(accL[nt], a2, b2);
            }
            // b-split mid: hm, mm -> accL
            lds128(bf,     bB + (unsigned)(((1 * 4 + kt) * 2 + nh) * 2 + 0) * 512 + lane * 16);
            lds128(bf + 4, bB + (unsigned)(((1 * 4 + kt) * 2 + nh) * 2 + 1) * 512 + lane * 16);
            #pragma unroll
            for (int nt = 0; nt < 4; ++nt) {
                const uint32_t* b2 = bf + (nt >> 1) * 4 + (nt & 1) * 2;
                mma16816(accL[nt], a0, b2);
                mma16816(accL[nt], a1, b2);
            }
            // b-split lo: hl -> accL
            lds128(bf,     bB + (unsigned)(((2 * 4 + kt) * 2 + nh) * 2 + 0) * 512 + lane * 16);
            lds128(bf + 4, bB + (unsigned)(((2 * 4 + kt) * 2 + nh) * 2 + 1) * 512 + lane * 16);
            #pragma unroll
            for (int nt = 0; nt < 4; ++nt) {
                const uint32_t* b2 = bf + (nt >> 1) * 4 + (nt & 1) * 2;
                mma16816(accL[nt], a0, b2);
            }
        }

        if (c + 2 < NCHUNK) loadB(c + 2); else cp_commit();
        if (c + 1 < NCHUNK) convertStore(xr, (c + 1) & 1);

        // fold accH into Kahan every chunk (chains of 4 mma-accum steps)
        #pragma unroll
        for (int nt = 0; nt < 4; ++nt)
            #pragma unroll
            for (int q = 0; q < 4; ++q) {
                float y = accH[nt][q] - kC[nt][q];
                float s = kS[nt][q] + y;
                kC[nt][q] = (s - kS[nt][q]) - y;
                kS[nt][q] = s;
                accH[nt][q] = 0.0f;
            }
    }

    // ---- write logits [128][66] ----
    float* lg = (float*)dynsm;
    #pragma unroll
    for (int nt = 0; nt < 4; ++nt) {
        int n0 = nh * 32 + nt * 8 + (lane & 3) * 2;
        int rl = mt * 16 + (lane >> 2);
        float f0 = kS[nt][0] + (accL[nt][0] - kC[nt][0]);
        float f1 = kS[nt][1] + (accL[nt][1] - kC[nt][1]);
        float f2 = kS[nt][2] + (accL[nt][2] - kC[nt][2]);
        float f3 = kS[nt][3] + (accL[nt][3] - kC[nt][3]);
        *(float2*)(lg + rl * 66 + n0)       = make_float2(f0, f1);
        *(float2*)(lg + (rl + 8) * 66 + n0) = make_float2(f2, f3);
    }
    __syncthreads();

    // ---- softmax + top-8: warp w -> tokens [8w, 8w+8) ----
    float ls0 = 0.0f, ls1 = 0.0f;
    int   c0  = 0,    c1  = 0;
    for (int t = w * 8; t < w * 8 + 8; ++t) {
        float l0 = lg[t * 66 + lane];
        float l1 = lg[t * 66 + 32 + lane];
        float m = fmaxf(l0, l1);
        #pragma unroll
        for (int off = 16; off; off >>= 1)
            m = fmaxf(m, __shfl_xor_sync(0xffffffffu, m, off));
        float s0 = expf(l0 - m), s1 = expf(l1 - m);
        float z = s0 + s1;
        #pragma unroll
        for (int off = 16; off; off >>= 1)
            z += __shfl_xor_sync(0xffffffffu, z, off);
        s0 /= z; s1 /= z;
        ls0 += s0; ls1 += s1;

        float r0 = s0, r1 = s1;
        float sumTop = 0.0f, myS = 0.0f;
        int myIdx = 0;
        #pragma unroll
        for (int r = 0; r < KTOP; ++r) {
            float v; int id;
            if (r0 >= r1) { v = r0; id = lane; }       // tie -> lower index
            else          { v = r1; id = lane + 32; }
            #pragma unroll
            for (int off = 16; off; off >>= 1) {
                float v2 = __shfl_xor_sync(0xffffffffu, v, off);
                int   i2 = __shfl_xor_sync(0xffffffffu, id, off);
                if (v2 > v || (v2 == v && i2 < id)) { v = v2; id = i2; }
            }
            sumTop += v;
            if (lane == r) { myS = v; myIdx = id; }
            if (id == lane)           { r0 = -1.0f; c0++; }
            else if (id == lane + 32) { r1 = -1.0f; c1++; }
        }
        if (lane < KTOP) {
            size_t gt = (size_t)(blockIdx.x * BM + t) * KTOP + lane;
            outIdx[gt] = (float)myIdx;
            outW[gt]   = myS / (sumTop + 1e-20f);
        }
    }

    // ---- CTA reduction + 64 global atomics ----
    float* redS = (float*)dynsm + 8448;          // beyond lg (128*66)
    float* redC = (float*)dynsm + 8448 + 1024;
    redS[w * 64 + lane]      = ls0;
    redS[w * 64 + lane + 32] = ls1;
    redC[w * 64 + lane]      = (float)c0;
    redC[w * 64 + lane + 32] = (float)c1;
    __syncthreads();
    if (tid < NEXP) {
        float es = 0.0f, ec = 0.0f;
        #pragma unroll
        for (int ww = 0; ww < 16; ++ww) {
            es += redS[ww * 64 + tid];
            ec += redC[ww * 64 + tid];
        }
        atomicAdd(&g_esum[tid], es);
        if (ec != 0.0f) atomicAdd(&g_ecnt[tid], (int)ec);
    }

    // ---- last-CTA aux finalize ----
    __shared__ unsigned s_isLast;
    __threadfence();
    __syncthreads();
    if (tid == 0)
        s_isLast = (atomicAdd(&g_done, 1u) == gridDim.x - 1) ? 1u : 0u;
    __syncthreads();
    if (s_isLast && tid < 32) {
        float p = g_esum[tid] * (float)g_ecnt[tid]
                + g_esum[tid + 32] * (float)g_ecnt[tid + 32];
        g_esum[tid] = 0.0f;  g_esum[tid + 32] = 0.0f;
        g_ecnt[tid] = 0;     g_ecnt[tid + 32] = 0;
        #pragma unroll
        for (int off = 16; off; off >>= 1)
            p += __shfl_xor_sync(0xffffffffu, p, off);
        if (tid == 0) {
            g_done = 0;
            float denom = (float)N * (float)(N * KTOP);
            *outAux = 0.01f * 64.0f * p / denom;   // ALPHA * E * sum / (N * N*K)
        }
    }
}

extern "C" void kernel_launch(void* const* d_in, const int* in_sizes, int n_in,
                              void* d_out, int out_size) {
    const float* X = (const float*)d_in[0];   // [4,8192,1024] f32
    const float* W = (const float*)d_in[1];   // [64,1024] f32
    float* out = (float*)d_out;               // [idx N*8 | weight N*8 | aux 1]
    int N = in_sizes[0] / HDIM;               // 32768

    cudaFuncSetAttribute(gate_k, cudaFuncAttributeMaxDynamicSharedMemorySize, SMEM_TOTAL);
    wsplit_k<<<NEXP * HDIM / 256, 256>>>(W);
    gate_k<<<N / BM, NTHREADS, SMEM_TOTAL>>>(X, out, out + (size_t)N * KTOP,
                                             out + (size_t)2 * N * KTOP, N);
}

// round 9
// speedup vs baseline: 5.9414x; 1.0015x over previous
#include <cuda_runtime.h>
#include <cuda_bf16.h>
#include <cstdint>

#define HDIM 1024
#define NEXP 64
#define KTOP 8
#define BM   128
#define KC   64
#define NCHUNK 16
#define NTHREADS 256

#define B_STAGE 24576                    // 3 splits x 4 kt x 2 nh x 2 ntp x 32 x 16B
#define SMEM_TOTAL (4 * B_STAGE)         // 98304 B (logits overlay after the loop)

__device__ unsigned short g_wp[3 * 64 * 2 * 2 * 32 * 8];  // W splits, frag-permuted
__device__ float    g_esum[NEXP];
__device__ int      g_ecnt[NEXP];
__device__ unsigned g_done = 0;

__device__ __forceinline__ unsigned smem_u32(const void* p) {
    return (unsigned)__cvta_generic_to_shared(p);
}
__device__ __forceinline__ void cp16(unsigned dst, const void* src) {
    asm volatile("cp.async.cg.shared.global [%0], [%1], 16;\n" :: "r"(dst), "l"(src));
}
__device__ __forceinline__ void cp_commit() { asm volatile("cp.async.commit_group;\n"); }
__device__ __forceinline__ void cp_wait1()  { asm volatile("cp.async.wait_group 1;\n" ::: "memory"); }

__device__ __forceinline__ uint32_t cvt_bf16x2(float hi, float lo) {  // hi -> upper half
    uint32_t d; asm("cvt.rn.bf16x2.f32 %0, %1, %2;" : "=r"(d) : "f"(hi), "f"(lo)); return d;
}
__device__ __forceinline__ float ubflo(uint32_t u) { return __uint_as_float(u << 16); }
__device__ __forceinline__ float ubfhi(uint32_t u) { return __uint_as_float(u & 0xFFFF0000u); }

__device__ __forceinline__ void lds128(uint32_t* r, unsigned a) {
    asm volatile("ld.shared.v4.u32 {%0,%1,%2,%3}, [%4];"
                 : "=r"(r[0]), "=r"(r[1]), "=r"(r[2]), "=r"(r[3]) : "r"(a));
}
// D(16x8,f32) += A(16x16,bf16 row) x B(16x8,bf16 col)
__device__ __forceinline__ void mma16816(float* d, const uint32_t* a, const uint32_t* b) {
    asm volatile("mma.sync.aligned.m16n8k16.row.col.f32.bf16.bf16.f32 "
                 "{%0,%1,%2,%3}, {%4,%5,%6,%7}, {%8,%9}, {%0,%1,%2,%3};"
                 : "+f"(d[0]), "+f"(d[1]), "+f"(d[2]), "+f"(d[3])
                 : "r"(a[0]), "r"(a[1]), "r"(a[2]), "r"(a[3]), "r"(b[0]), "r"(b[1]));
}

// Split W (rounded 3-way) and store in B-fragment-permuted layout (proven in R8).
__global__ void wsplit_k(const float* __restrict__ W) {
    int i = blockIdx.x * 256 + threadIdx.x;   // i = n*1024 + k
    int n = i >> 10, k = i & 1023;
    float x = W[i];
    __nv_bfloat16 bh = __float2bfloat16_rn(x);
    float r1 = x - __bfloat162float(bh);
    __nv_bfloat16 bm = __float2bfloat16_rn(r1);
    float r2 = r1 - __bfloat162float(bm);
    __nv_bfloat16 bl = __float2bfloat16_rn(r2);
    unsigned short hv[3];
    hv[0] = *reinterpret_cast<unsigned short*>(&bh);
    hv[1] = *reinterpret_cast<unsigned short*>(&bm);
    hv[2] = *reinterpret_cast<unsigned short*>(&bl);

    int kt = k >> 4, kl = k & 15;
    int lane = ((n & 7) << 2) | ((kl >> 1) & 3);
    int reg  = (kl >> 3) & 1;
    int nh   = n >> 5, ntp = (n >> 4) & 1;
    int w4   = ((n >> 3) & 1) * 2 + reg;
    #pragma unroll
    for (int s = 0; s < 3; ++s) {
        size_t off = ((((size_t)s * 64 + kt) * 2 + nh) * 2 + ntp) * 32 + lane;  // 16B units
        g_wp[off * 8 + w4 * 2 + (kl & 1)] = hv[s];
    }
}

extern __shared__ char dynsm[];

__global__ __launch_bounds__(NTHREADS, 1)
void gate_k(const float* __restrict__ X,
            float* __restrict__ outIdx, float* __restrict__ outW,
            float* __restrict__ outAux, int N) {
    const int tid  = threadIdx.x;
    const int lane = tid & 31;
    const int w    = tid >> 5;          // warp = m-tile (16 tokens), all 64 experts
    const unsigned sbu = smem_u32(dynsm);

    // this lane's A-fragment source rows/cols in X
    const float* Xw = X + (size_t)blockIdx.x * BM * HDIM
                        + (size_t)(w * 16 + (lane >> 2)) * HDIM + (lane & 3) * 2;

    auto loadB = [&](int c) {
        #pragma unroll
        for (int t = 0; t < 6; ++t) {
            int j = tid + t * 256;                  // 1536 16B units per stage
            int s = j >> 9, rem = j & 511;
            cp16(sbu + (c & 3) * B_STAGE + (unsigned)j * 16,
                 (const char*)g_wp + (((size_t)s * 64 + c * 4) * 128 + rem) * 16);
        }
        cp_commit();
    };
    auto loadX = [&](int c, float2* xv) {
        const float* p = Xw + c * KC;
        #pragma unroll
        for (int kt = 0; kt < 4; ++kt) {
            xv[kt * 4 + 0] = *(const float2*)(p + kt * 16);
            xv[kt * 4 + 1] = *(const float2*)(p + kt * 16 + 8);
            xv[kt * 4 + 2] = *(const float2*)(p + kt * 16 + 8 * HDIM);
            xv[kt * 4 + 3] = *(const float2*)(p + kt * 16 + 8 * HDIM + 8);
        }
    };

    float2 xc[16], xn[16];
    loadX(0, xc);
    loadB(0);
    loadB(1);

    float accH[8][4] = {}, accL[8][4] = {}, kS[8][4] = {};

    for (int c = 0; c < NCHUNK; ++c) {
        cp_wait1();         // B stage c landed (stage c+1 may still be in flight)
        __syncthreads();    // all warps past stage (c-2) reads -> safe to refill

        if (c + 1 < NCHUNK) loadX(c + 1, xn);

        const unsigned bB = sbu + (c & 3) * B_STAGE;
        #pragma unroll
        for (int kt = 0; kt < 4; ++kt) {
            // convert this kt's 8 f32 values -> 3 bf16x2 fragments, in registers
            uint32_t ah[4], am[4], aq[4];
            {
                const int src[4] = { 4 * kt + 0, 4 * kt + 2, 4 * kt + 1, 4 * kt + 3 };
                #pragma unroll
                for (int f = 0; f < 4; ++f) {
                    float2 v = xc[src[f]];
                    uint32_t h = cvt_bf16x2(v.y, v.x);
                    float r1x = v.x - ubflo(h), r1y = v.y - ubfhi(h);
                    uint32_t m = cvt_bf16x2(r1y, r1x);
                    float r2x = r1x - ubflo(m), r2y = r1y - ubfhi(m);
                    ah[f] = h; am[f] = m;
                    aq[f] = cvt_bf16x2(r2y, r2x);
                }
            }
            // B split hi: hh -> accH ; mh, lh -> accL
            #pragma unroll
            for (int qd = 0; qd < 4; ++qd) {
                uint32_t bf[4];
                lds128(bf, bB + (unsigned)(((((0 * 4 + kt) * 2 + (qd >> 1)) * 2 + (qd & 1)) * 32 + lane) * 16));
                mma16816(accH[qd * 2],     ah, bf);
                mma16816(accH[qd * 2 + 1], ah, bf + 2);
                mma16816(accL[qd * 2],     am, bf);
                mma16816(accL[qd * 2 + 1], am, bf + 2);
                mma16816(accL[qd * 2],     aq, bf);
                mma16816(accL[qd * 2 + 1], aq, bf + 2);
            }
            // B split mid: hm, mm -> accL
            #pragma unroll
            for (int qd = 0; qd < 4; ++qd) {
                uint32_t bf[4];
                lds128(bf, bB + (unsigned)(((((1 * 4 + kt) * 2 + (qd >> 1)) * 2 + (qd & 1)) * 32 + lane) * 16));
                mma16816(accL[qd * 2],     ah, bf);
                mma16816(accL[qd * 2 + 1], ah, bf + 2);
                mma16816(accL[qd * 2],     am, bf);
                mma16816(accL[qd * 2 + 1], am, bf + 2);
            }
            // B split lo: hl -> accL
            #pragma unroll
            for (int qd = 0; qd < 4; ++qd) {
                uint32_t bf[4];
                lds128(bf, bB + (unsigned)(((((2 * 4 + kt) * 2 + (qd >> 1)) * 2 + (qd & 1)) * 32 + lane) * 16));
                mma16816(accL[qd * 2],     ah, bf);
                mma16816(accL[qd * 2 + 1], ah, bf + 2);
            }
        }

        if (c + 2 < NCHUNK) loadB(c + 2); else cp_commit();
        #pragma unroll
        for (int i = 0; i < 16; ++i) xc[i] = xn[i];

        if (c & 1) {  // fold accH partial (8 accumulate steps) into master sums
            #pragma unroll
            for (int nt = 0; nt < 8; ++nt)
                #pragma unroll
                for (int q = 0; q < 4; ++q) { kS[nt][q] += accH[nt][q]; accH[nt][q] = 0.0f; }
        }
    }
    __syncthreads();   // everyone done with B smem -> overlay logits

    // ---- write logits [128][66] ----
    float* lg = (float*)dynsm;
    {
        int r0 = w * 16 + (lane >> 2);
        int n0 = (lane & 3) * 2;
        #pragma unroll
        for (int nt = 0; nt < 8; ++nt) {
            float f0 = kS[nt][0] + accL[nt][0];
            float f1 = kS[nt][1] + accL[nt][1];
            float f2 = kS[nt][2] + accL[nt][2];
            float f3 = kS[nt][3] + accL[nt][3];
            *(float2*)(lg + r0 * 66 + nt * 8 + n0)       = make_float2(f0, f1);
            *(float2*)(lg + (r0 + 8) * 66 + nt * 8 + n0) = make_float2(f2, f3);
        }
    }
    __syncthreads();

    // ---- softmax + top-8: warp w -> tokens [16w, 16w+16) ----
    float ls0 = 0.0f, ls1 = 0.0f;
    int   c0  = 0,    c1  = 0;
    for (int t = w * 16; t < w * 16 + 16; ++t) {
        float l0 = lg[t * 66 + lane];
        float l1 = lg[t * 66 + 32 + lane];
        float m = fmaxf(l0, l1);
        #pragma unroll
        for (int off = 16; off; off >>= 1)
            m = fmaxf(m, __shfl_xor_sync(0xffffffffu, m, off));
        float s0 = expf(l0 - m), s1 = expf(l1 - m);
        float z = s0 + s1;
        #pragma unroll
        for (int off = 16; off; off >>= 1)
            z += __shfl_xor_sync(0xffffffffu, z, off);
        s0 /= z; s1 /= z;
        ls0 += s0; ls1 += s1;

        float r0 = s0, r1 = s1;
        float sumTop = 0.0f, myS = 0.0f;
        int myIdx = 0;
        #pragma unroll
        for (int r = 0; r < KTOP; ++r) {
            float v; int id;
            if (r0 >= r1) { v = r0; id = lane; }       // tie -> lower index
            else          { v = r1; id = lane + 32; }
            #pragma unroll
            for (int off = 16; off; off >>= 1) {
                float v2 = __shfl_xor_sync(0xffffffffu, v, off);
                int   i2 = __shfl_xor_sync(0xffffffffu, id, off);
                if (v2 > v || (v2 == v && i2 < id)) { v = v2; id = i2; }
            }
            sumTop += v;
            if (lane == r) { myS = v; myIdx = id; }
            if (id == lane)           { r0 = -1.0f; c0++; }
            else if (id == lane + 32) { r1 = -1.0f; c1++; }
        }
        if (lane < KTOP) {
            size_t gt = (size_t)(blockIdx.x * BM + t) * KTOP + lane;
            outIdx[gt] = (float)myIdx;
            outW[gt]   = myS / (sumTop + 1e-20f);
        }
    }

    // ---- CTA reduction + 64 global atomics ----
    float* redS = (float*)dynsm + 8448;          // beyond lg (128*66)
    float* redC = redS + 512;
    redS[w * 64 + lane]      = ls0;
    redS[w * 64 + lane + 32] = ls1;
    redC[w * 64 + lane]      = (float)c0;
    redC[w * 64 + lane + 32] = (float)c1;
    __syncthreads();
    if (tid < NEXP) {
        float es = 0.0f, ec = 0.0f;
        #pragma unroll
        for (int ww = 0; ww < 8; ++ww) {
            es += redS[ww * 64 + tid];
            ec += redC[ww * 64 + tid];
        }
        atomicAdd(&g_esum[tid], es);
        if (ec != 0.0f) atomicAdd(&g_ecnt[tid], (int)ec);
    }

    // ---- last-CTA aux finalize ----
    __shared__ unsigned s_isLast;
    __threadfence();
    __syncthreads();
    if (tid == 0)
        s_isLast = (atomicAdd(&g_done, 1u) == gridDim.x - 1) ? 1u : 0u;
    __syncthreads();
    if (s_isLast && tid < 32) {
        float p = g_esum[tid] * (float)g_ecnt[tid]
                + g_esum[tid + 32] * (float)g_ecnt[tid + 32];
        g_esum[tid] = 0.0f;  g_esum[tid + 32] = 0.0f;
        g_ecnt[tid] = 0;     g_ecnt[tid + 32] = 0;
        #pragma unroll
        for (int off = 16; off; off >>= 1)
            p += __shfl_xor_sync(0xffffffffu, p, off);
        if (tid == 0) {
            g_done = 0;
            float denom = (float)N * (float)(N * KTOP);
            *outAux = 0.01f * 64.0f * p / denom;   // ALPHA * E * sum / (N * N*K)
        }
    }
}

extern "C" void kernel_launch(void* const* d_in, const int* in_sizes, int n_in,
                              void* d_out, int out_size) {
    const float* X = (const float*)d_in[0];   // [4,8192,1024] f32
    const float* W = (const float*)d_in[1];   // [64,1024] f32
    float* out = (float*)d_out;               // [idx N*8 | weight N*8 | aux 1]
    int N = in_sizes[0] / HDIM;               // 32768

    cudaFuncSetAttribute(gate_k, cudaFuncAttributeMaxDynamicSharedMemorySize, SMEM_TOTAL);
    wsplit_k<<<NEXP * HDIM / 256, 256>>>(W);
    gate_k<<<N / BM, NTHREADS, SMEM_TOTAL>>>(X, out, out + (size_t)N * KTOP,
                                             out + (size_t)2 * N * KTOP, N);
}